// round 16
// baseline (speedup 1.0000x reference)
#include <cuda_runtime.h>
#include <cuda_fp16.h>

#define NQ 20
typedef unsigned long long u64;
typedef unsigned int u32;

// 64MB scratch: fp16x2 intermediate, PERMUTED low-10 layout:
//   s = (e bits 2..6)<<5 | (e bit9)<<4 | (e bit8)<<3 | (e bit7)<<2 | (e bits 0..1)
__device__ u32 g_scratch[16u << 20];

// ---------------- f32x2 helpers (packed 2xfp32 ops, sm_103a) ----------------
__device__ __forceinline__ u64 pk(float lo, float hi) {
    u64 r; asm("mov.b64 %0,{%1,%2};" : "=l"(r) : "f"(lo), "f"(hi)); return r;
}
__device__ __forceinline__ void upk(u64 p, float& lo, float& hi) {
    asm("mov.b64 {%0,%1},%2;" : "=f"(lo), "=f"(hi) : "l"(p));
}
__device__ __forceinline__ u64 f2mul(u64 a, u64 b) {
    u64 r; asm("mul.rn.f32x2 %0,%1,%2;" : "=l"(r) : "l"(a), "l"(b)); return r;
}
__device__ __forceinline__ u64 f2fma(u64 a, u64 b, u64 c) {
    u64 r; asm("fma.rn.f32x2 %0,%1,%2,%3;" : "=l"(r) : "l"(a), "l"(b), "l"(c)); return r;
}

// ---------------- fast-Givens RX stages ----------------
// Unscaled update with t = tan(th/2):
//   ax' = ax + t*by ; ay' = ay - t*bx ; bx' = bx + t*ay ; by' = by - t*ax
// True result = (prod of cos) * unscaled; scale applied once per pass.

// intra-pack stage (butterfly partner inside the f32x2 pack)
__device__ __forceinline__ void stage0_fg(u64 PX[16], u64 PY[16], float tt)
{
#pragma unroll
    for (int q = 0; q < 16; ++q) {
        float xl, xh, yl, yh;
        upk(PX[q], xl, xh); upk(PY[q], yl, yh);
        PX[q] = pk(fmaf(tt, yh, xl), fmaf(tt, yl, xh));
        PY[q] = pk(fmaf(-tt, xh, yl), fmaf(-tt, xl, yh));
    }
}

// pack-level stages with pack masks 1,2,4,8 using t[1..4]
__device__ __forceinline__ void stages_fg_tail(u64 PX[16], u64 PY[16], const float t[5])
{
#pragma unroll
    for (int j = 1; j < 5; ++j) {
        u64 t2  = pk(t[j],  t[j]);
        u64 tn2 = pk(-t[j], -t[j]);
        const int pm = 1 << (j - 1);
#pragma unroll
        for (int q = 0; q < 16; ++q) {
            if (!(q & pm)) {
                const int q2 = q | pm;
                u64 ax = PX[q], bx = PX[q2];
                PX[q]  = f2fma(t2,  PY[q2], ax);
                PX[q2] = f2fma(t2,  PY[q],  bx);
                PY[q]  = f2fma(tn2, bx, PY[q]);
                PY[q2] = f2fma(tn2, ax, PY[q2]);
            }
        }
    }
}

__device__ __forceinline__ void scale_all(u64 PX[16], u64 PY[16], float C)
{
    u64 C2 = pk(C, C);
#pragma unroll
    for (int q = 0; q < 16; ++q) {
        PX[q] = f2mul(C2, PX[q]);
        PY[q] = f2mul(C2, PY[q]);
    }
}

// load t = tan(th/2) for an arbitrary list of global bits; returns prod cos.
// qubit i = most-significant bit => global bit g maps to theta index (19-g)
__device__ __forceinline__ float load_tc_bits(const float* __restrict__ thetas,
                                              int b, const int gb[5], float t[5])
{
    float C = 1.0f;
#pragma unroll
    for (int j = 0; j < 5; ++j) {
        float th = thetas[b * NQ + (NQ - 1 - gb[j])];
        float s, c;
        __sincosf(0.5f * th, &s, &c);
        t[j] = __fdividef(s, c);
        C *= c;
    }
    return C;
}

__device__ __forceinline__ float load_tc(const float* __restrict__ thetas, int b,
                                         int gbase, float t[5])
{
    const int gb[5] = {gbase, gbase + 1, gbase + 2, gbase + 3, gbase + 4};
    return load_tc_bits(thetas, b, gb, t);
}

// ---------------------------------------------------------------------------
// Pass A v2: global bits 0..9, all 16 batches, COALESCED loads.
// Warp owns 1024 contiguous elements; instr k loads 512B contiguous
// (e = k<<7 | lane<<2 | j) -> 4 L1 wavefronts/instr instead of 32.
// Phase 1 butterflies bits {0,1,7,8,9} (the in-register bits of this shape);
// conflict-free padded transpose (addr = e + (e>>5)); phase 2 bits {2..6}.
// Scratch written coalesced in PERMUTED layout s = r2*32 + lane
// (lane = bits {0,1,7,8,9} of e, r2 = bits 2..6).
// ---------------------------------------------------------------------------
__global__ void __launch_bounds__(256)
rx_a(const float* __restrict__ phi, const float* __restrict__ thetas)
{
    __shared__ float sm[8][1056];              // 1024 + 32 pad per warp
    const int w    = threadIdx.x >> 5;
    const int lane = threadIdx.x & 31;
    const u32 gw   = blockIdx.x * 8 + w;       // 16384 warps
    const int b    = gw >> 10;
    const u32 base = gw << 10;

    // phase-1 bits {0,1,7,8,9} (intra-pack bit 0; masks 1,2,4,8 -> 1,7,8,9)
    const int gb1[5] = {0, 1, 7, 8, 9};
    // phase-2 bits {2,3,4,5,6} (intra-pack bit 2; masks -> 3,4,5,6)
    const int gb2[5] = {2, 3, 4, 5, 6};
    float t1[5], t2[5];
    float C1 = load_tc_bits(thetas, b, gb1, t1);
    float C2 = load_tc_bits(thetas, b, gb2, t2);
    const float Ct = C1 * C2;

    // coalesced loads: instr k covers elements [k*128, k*128+128)
    u64 PX[16], PY[16];
    const float4* p4 = reinterpret_cast<const float4*>(phi + base);
#pragma unroll
    for (int k = 0; k < 8; ++k) {
        float4 v = __ldcs(p4 + k * 32 + lane); // e = k<<7 | lane<<2 | j
        PX[2 * k]     = pk(v.x, v.y);          // j = 0,1  (pack q = k<<1)
        PX[2 * k + 1] = pk(v.z, v.w);          // j = 2,3  (pack q = k<<1|1)
    }

    // phase 1, input real: stage0 (gbit 0) specialized: PY = -t * swap(PX)
    {
        const float tn = -t1[0];
#pragma unroll
        for (int q = 0; q < 16; ++q) {
            float xl, xh; upk(PX[q], xl, xh);
            PY[q] = pk(tn * xh, tn * xl);
        }
    }
    stages_fg_tail(PX, PY, t1);    // gbits 1,7,8,9

    // transpose via padded smem: addr(e) = e + (e>>5)
    //   store (reg r fixed): addr = (r>>2)*132 + (r&3) + lane*4 + (lane>>3)
    //   read  (reg r2 fixed): addr = r2*4 + (r2>>3) + (lane>>2)*132 + (lane&3)
    float* X = sm[w];
    const int sb = lane * 4 + (lane >> 3);           // store base
    const int rb = (lane >> 2) * 132 + (lane & 3);   // read base
#pragma unroll
    for (int q = 0; q < 16; ++q) {
        float xl, xh; upk(PX[q], xl, xh);
        const int rA = 2 * q, rB = 2 * q + 1;
        X[(rA >> 2) * 132 + (rA & 3) + sb] = xl;
        X[(rB >> 2) * 132 + (rB & 3) + sb] = xh;
    }
    __syncwarp();
#pragma unroll
    for (int q = 0; q < 16; ++q) {
        const int rA = 2 * q, rB = 2 * q + 1;
        PX[q] = pk(X[rA * 4 + (rA >> 3) + rb], X[rB * 4 + (rB >> 3) + rb]);
    }
    __syncwarp();
#pragma unroll
    for (int q = 0; q < 16; ++q) {
        float yl, yh; upk(PY[q], yl, yh);
        const int rA = 2 * q, rB = 2 * q + 1;
        X[(rA >> 2) * 132 + (rA & 3) + sb] = yl;
        X[(rB >> 2) * 132 + (rB & 3) + sb] = yh;
    }
    __syncwarp();
#pragma unroll
    for (int q = 0; q < 16; ++q) {
        const int rA = 2 * q, rB = 2 * q + 1;
        PY[q] = pk(X[rA * 4 + (rA >> 3) + rb], X[rB * 4 + (rB >> 3) + rb]);
    }

    stage0_fg(PX, PY, t2[0]);      // gbit 2
    stages_fg_tail(PX, PY, t2);    // gbits 3,4,5,6

    scale_all(PX, PY, Ct);

    // coalesced scratch store in permuted layout: s = r2*32 + lane
#pragma unroll
    for (int q = 0; q < 16; ++q) {
        float xl, xh, yl, yh;
        upk(PX[q], xl, xh); upk(PY[q], yl, yh);
        __half2 h0 = __floats2half2_rn(xl, yl);
        __half2 h1 = __floats2half2_rn(xh, yh);
        g_scratch[base + (2 * q) * 32 + lane]     = *reinterpret_cast<u32*>(&h0);
        g_scratch[base + (2 * q + 1) * 32 + lane] = *reinterpret_cast<u32*>(&h1);
    }
}

// ---------------------------------------------------------------------------
// Pass B (R7 structure): global bits 10..19, all 16 batches.
// Scratch reads __ldcs in s-space (layout permutation is transparent to the
// high bits). Single-barrier STS64 pack transpose. Final stores un-permute
// the low-10 bits: true = (w>>2)<<7 | v<<2 | (w&3) for s = v<<5 | w.
// ---------------------------------------------------------------------------
__global__ void __launch_bounds__(256)
rx_b(const float* __restrict__ thetas, float2* __restrict__ out)
{
    __shared__ u64 smq[2 * 32 * 136];          // 69632 B
    const int t   = threadIdx.x;
    const int low = t & 7;
    const int g5  = t >> 3;
    const int blk   = blockIdx.x;              // 2048 blocks
    const int b     = blk >> 7;
    const int chunk = blk & 127;
    const u32 s10   = ((u32)chunk << 3) | (u32)low;        // s-space low-10
    const u32 base  = ((u32)b << 20) + s10;                // scratch address

    // un-permute for the output store
    const u32 w5 = s10 & 31, v5 = s10 >> 5;
    const u32 tru10 = ((w5 >> 2) << 7) | (v5 << 2) | (w5 & 3);
    const u32 obase = ((u32)b << 20) + tru10;

    float t1[5];
    float C1 = load_tc(thetas, b, 10, t1);

    // loads: two batches of 16 issued before their converts (MLP)
    u64 PX[16], PY[16];
    const u32 a0 = base + ((u32)g5 << 15);
#pragma unroll
    for (int h = 0; h < 2; ++h) {
        u32 wv[16];
#pragma unroll
        for (int k = 0; k < 16; ++k)
            wv[k] = __ldcs(&g_scratch[a0 + (u32)(h * 16 + k) * 1024u]);
#pragma unroll
        for (int k = 0; k < 8; ++k) {
            const int q = h * 8 + k;
            float2 v0 = __half22float2(*reinterpret_cast<__half2*>(&wv[2 * k]));
            float2 v1 = __half22float2(*reinterpret_cast<__half2*>(&wv[2 * k + 1]));
            PX[q] = pk(v0.x, v1.x);
            PY[q] = pk(v0.y, v1.y);
        }
    }

    stage0_fg(PX, PY, t1[0]);      // bit 10
    stages_fg_tail(PX, PY, t1);    // bits 11..14

    // pack-store X and Y (STS64), one barrier
#pragma unroll
    for (int q = 0; q < 16; ++q) {
        smq[g5 * 136 + q * 8 + low]              = PX[q];
        smq[32 * 136 + g5 * 136 + q * 8 + low]   = PY[q];
    }
    __syncthreads();

    const float* smf = reinterpret_cast<const float*>(smq);
    const int ro = ((g5 >> 1) << 4) + (low << 1) + (g5 & 1);
#pragma unroll
    for (int q = 0; q < 16; ++q) {
        PX[q] = pk(smf[(2 * q) * 272 + ro],        smf[(2 * q + 1) * 272 + ro]);
        PY[q] = pk(smf[8704 + (2 * q) * 272 + ro], smf[8704 + (2 * q + 1) * 272 + ro]);
    }

    float t2[5];
    float C2 = load_tc(thetas, b, 15, t2);

    stage0_fg(PX, PY, t2[0]);      // bit 15
    stages_fg_tail(PX, PY, t2);    // bits 16..19

    scale_all(PX, PY, C1 * C2);

    const u32 a1 = obase + ((u32)g5 << 10);
#pragma unroll
    for (int q = 0; q < 16; ++q) {
        float xl, xh, yl, yh;
        upk(PX[q], xl, xh); upk(PY[q], yl, yh);
        __stcs(&out[a1 + ((u32)(2 * q) << 15)],     make_float2(xl, yl));
        __stcs(&out[a1 + ((u32)(2 * q + 1) << 15)], make_float2(xh, yh));
    }
}

// ---------------------------------------------------------------------------
extern "C" void kernel_launch(void* const* d_in, const int* in_sizes, int n_in,
                              void* d_out, int out_size)
{
    const float* phi    = (const float*)d_in[0];   // [16, 2^20] float32
    const float* thetas = (const float*)d_in[1];   // [16, 20]   float32
    float2* out = (float2*)d_out;                  // [16, 2^20] (re, im)

    rx_a<<<2048, 256>>>(phi, thetas);
    rx_b<<<2048, 256>>>(thetas, out);
}

// round 17
// speedup vs baseline: 1.1234x; 1.1234x over previous
#include <cuda_runtime.h>
#include <cuda_fp16.h>

#define NQ 20
typedef unsigned long long u64;
typedef unsigned int u32;

// 64MB scratch: fp16x2 intermediate for all 16 batches (normal layout)
__device__ u32 g_scratch[16u << 20];

// ---------------- f32x2 helpers (packed 2xfp32 ops, sm_103a) ----------------
__device__ __forceinline__ u64 pk(float lo, float hi) {
    u64 r; asm("mov.b64 %0,{%1,%2};" : "=l"(r) : "f"(lo), "f"(hi)); return r;
}
__device__ __forceinline__ void upk(u64 p, float& lo, float& hi) {
    asm("mov.b64 {%0,%1},%2;" : "=f"(lo), "=f"(hi) : "l"(p));
}
__device__ __forceinline__ u64 f2mul(u64 a, u64 b) {
    u64 r; asm("mul.rn.f32x2 %0,%1,%2;" : "=l"(r) : "l"(a), "l"(b)); return r;
}
__device__ __forceinline__ u64 f2fma(u64 a, u64 b, u64 c) {
    u64 r; asm("fma.rn.f32x2 %0,%1,%2,%3;" : "=l"(r) : "l"(a), "l"(b), "l"(c)); return r;
}

// ---------------- fast-Givens RX stages ----------------
// Unscaled update with t = tan(th/2):
//   ax' = ax + t*by ; ay' = ay - t*bx ; bx' = bx + t*ay ; by' = by - t*ax
// True result = (prod of cos) * unscaled; scale applied once per pass.

// stage 0: element mask 1 (intra-pack), scalar fma on the halves
__device__ __forceinline__ void stage0_fg(u64 PX[16], u64 PY[16], float tt)
{
#pragma unroll
    for (int q = 0; q < 16; ++q) {
        float xl, xh, yl, yh;
        upk(PX[q], xl, xh); upk(PY[q], yl, yh);
        PX[q] = pk(fmaf(tt, yh, xl), fmaf(tt, yl, xh));
        PY[q] = pk(fmaf(-tt, xh, yl), fmaf(-tt, xl, yh));
    }
}

// stages 1..4: pack-level pairs, 4 f2fma per pair
__device__ __forceinline__ void stages_fg_tail(u64 PX[16], u64 PY[16], const float t[5])
{
#pragma unroll
    for (int j = 1; j < 5; ++j) {
        u64 t2  = pk(t[j],  t[j]);
        u64 tn2 = pk(-t[j], -t[j]);
        const int pm = 1 << (j - 1);
#pragma unroll
        for (int q = 0; q < 16; ++q) {
            if (!(q & pm)) {
                const int q2 = q | pm;
                u64 ax = PX[q], bx = PX[q2];
                PX[q]  = f2fma(t2,  PY[q2], ax);
                PX[q2] = f2fma(t2,  PY[q],  bx);
                PY[q]  = f2fma(tn2, bx, PY[q]);
                PY[q2] = f2fma(tn2, ax, PY[q2]);
            }
        }
    }
}

__device__ __forceinline__ void scale_all(u64 PX[16], u64 PY[16], float C)
{
    u64 C2 = pk(C, C);
#pragma unroll
    for (int q = 0; q < 16; ++q) {
        PX[q] = f2mul(C2, PX[q]);
        PY[q] = f2mul(C2, PY[q]);
    }
}

// qubit i = most-significant bit => global bit g maps to theta index (19-g)
__device__ __forceinline__ float load_tc(const float* __restrict__ thetas, int b,
                                         int gbit_base, float t[5])
{
    float C = 1.0f;
#pragma unroll
    for (int j = 0; j < 5; ++j) {
        float th = thetas[b * NQ + (NQ - 1 - (gbit_base + j))];
        float s, c;
        __sincosf(0.5f * th, &s, &c);
        t[j] = __fdividef(s, c);
        C *= c;
    }
    return C;
}

// ---------------------------------------------------------------------------
// Pass A (R7 + coalesced-load staging): global bits 0..9, all 16 batches.
// Global load is COALESCED (instr k reads 512B contiguous: elements
// k*128 + lane*4 .. +3 -> 4 L1 wavefronts instead of 32), then a
// warp-private smem stage re-deals elements into R7's register assignment
// (pack q <- elements lane*32+2q). Staging layout addr = e + 4*(e>>5):
//   STS.128 conflict-free per quarter-warp; LDS.128 at lane*36+4k
//   conflict-free and 16B aligned.
// Everything after the staging is R7-verbatim.
// ---------------------------------------------------------------------------
__global__ void __launch_bounds__(256)
rx_a(const float* __restrict__ phi, const float* __restrict__ thetas)
{
    __shared__ float sm[8][1152];              // staging (<=1148) + transpose (<=1086)
    const int w    = threadIdx.x >> 5;
    const int lane = threadIdx.x & 31;
    const u32 gw   = blockIdx.x * 8 + w;       // 16384 warps
    const int b    = gw >> 10;
    const u32 base = gw << 10;

    float t1[5], t2[5];
    float C1 = load_tc(thetas, b, 0, t1);
    float C2 = load_tc(thetas, b, 5, t2);
    const float Ct = C1 * C2;

    float* S = sm[w];

    // coalesced global load -> staged smem
    const float4* p4 = reinterpret_cast<const float4*>(phi + base);
#pragma unroll
    for (int k = 0; k < 8; ++k) {
        float4 v = __ldcs(p4 + k * 32 + lane);       // elements k*128 + lane*4 ..+3
        const int e0 = k * 128 + lane * 4;
        *reinterpret_cast<float4*>(&S[e0 + 4 * (e0 >> 5)]) = v;
    }
    __syncwarp();

    // re-deal: pack q <- elements (lane*32 + 2q, lane*32 + 2q + 1)
    u64 PX[16], PY[16];
#pragma unroll
    for (int k = 0; k < 8; ++k) {
        const int e0 = lane * 32 + 4 * k;            // addr = lane*36 + 4k
        float4 v = *reinterpret_cast<const float4*>(&S[e0 + 4 * (e0 >> 5)]);
        PX[2 * k]     = pk(v.x, v.y);
        PX[2 * k + 1] = pk(v.z, v.w);
    }
    __syncwarp();                                    // staging consumed before reuse

    // specialized stage 0 with imag = 0: PX unchanged, PY = -t * swap(PX)
    {
        const float tn = -t1[0];
#pragma unroll
        for (int q = 0; q < 16; ++q) {
            float xl, xh; upk(PX[q], xl, xh);
            PY[q] = pk(tn * xh, tn * xl);
        }
    }
    stages_fg_tail(PX, PY, t1);    // bits 1..4

    float* X = S;
#pragma unroll
    for (int q = 0; q < 16; ++q) {
        float l, h; upk(PX[q], l, h);
        X[(2 * q) * 34 + lane]     = l;
        X[(2 * q + 1) * 34 + lane] = h;
    }
    __syncwarp();
#pragma unroll
    for (int q = 0; q < 16; ++q) {
        float2 v = *reinterpret_cast<float2*>(&X[lane * 34 + 2 * q]);
        PX[q] = pk(v.x, v.y);
    }
    __syncwarp();
#pragma unroll
    for (int q = 0; q < 16; ++q) {
        float l, h; upk(PY[q], l, h);
        X[(2 * q) * 34 + lane]     = l;
        X[(2 * q + 1) * 34 + lane] = h;
    }
    __syncwarp();
#pragma unroll
    for (int q = 0; q < 16; ++q) {
        float2 v = *reinterpret_cast<float2*>(&X[lane * 34 + 2 * q]);
        PY[q] = pk(v.x, v.y);
    }

    stage0_fg(PX, PY, t2[0]);      // bit 5
    stages_fg_tail(PX, PY, t2);    // bits 6..9

    scale_all(PX, PY, Ct);         // apply deferred cos product once

#pragma unroll
    for (int q = 0; q < 16; ++q) {
        float xl, xh, yl, yh;
        upk(PX[q], xl, xh); upk(PY[q], yl, yh);
        __half2 h0 = __floats2half2_rn(xl, yl);
        __half2 h1 = __floats2half2_rn(xh, yh);
        g_scratch[base + (2 * q) * 32 + lane]     = *reinterpret_cast<u32*>(&h0);
        g_scratch[base + (2 * q + 1) * 32 + lane] = *reinterpret_cast<u32*>(&h1);
    }
}

// ---------------------------------------------------------------------------
// Pass B (R7 verbatim): global bits 10..19, all 16 batches.
// Reads fp16x2 intermediate with __ldcs, writes final fp32 out (__stcs).
// Single-barrier transpose: X and Y pack-stored (STS64) into two smem
// regions, one __syncthreads, then 32-bit gathers.
// ---------------------------------------------------------------------------
__global__ void __launch_bounds__(256)
rx_b(const float* __restrict__ thetas, float2* __restrict__ out)
{
    __shared__ u64 smq[2 * 32 * 136];          // 69632 B
    const int t   = threadIdx.x;
    const int low = t & 7;
    const int g5  = t >> 3;
    const int blk   = blockIdx.x;              // 2048 blocks
    const int b     = blk >> 7;
    const int chunk = blk & 127;
    const u32 base  = ((u32)b << 20) + ((u32)chunk << 3) + (u32)low;

    float t1[5];
    float C1 = load_tc(thetas, b, 10, t1);

    // loads: two batches of 16 issued before their converts (MLP)
    u64 PX[16], PY[16];
    const u32 a0 = base + ((u32)g5 << 15);
#pragma unroll
    for (int h = 0; h < 2; ++h) {
        u32 wv[16];
#pragma unroll
        for (int k = 0; k < 16; ++k)
            wv[k] = __ldcs(&g_scratch[a0 + (u32)(h * 16 + k) * 1024u]);
#pragma unroll
        for (int k = 0; k < 8; ++k) {
            const int q = h * 8 + k;
            float2 v0 = __half22float2(*reinterpret_cast<__half2*>(&wv[2 * k]));
            float2 v1 = __half22float2(*reinterpret_cast<__half2*>(&wv[2 * k + 1]));
            PX[q] = pk(v0.x, v1.x);
            PY[q] = pk(v0.y, v1.y);
        }
    }

    stage0_fg(PX, PY, t1[0]);      // bit 10
    stages_fg_tail(PX, PY, t1);    // bits 11..14

    // pack-store X and Y (STS64), one barrier
#pragma unroll
    for (int q = 0; q < 16; ++q) {
        smq[g5 * 136 + q * 8 + low]              = PX[q];
        smq[32 * 136 + g5 * 136 + q * 8 + low]   = PY[q];
    }
    __syncthreads();

    const float* smf = reinterpret_cast<const float*>(smq);
    const int ro = ((g5 >> 1) << 4) + (low << 1) + (g5 & 1);
#pragma unroll
    for (int q = 0; q < 16; ++q) {
        PX[q] = pk(smf[(2 * q) * 272 + ro],        smf[(2 * q + 1) * 272 + ro]);
        PY[q] = pk(smf[8704 + (2 * q) * 272 + ro], smf[8704 + (2 * q + 1) * 272 + ro]);
    }

    float t2[5];
    float C2 = load_tc(thetas, b, 15, t2);

    stage0_fg(PX, PY, t2[0]);      // bit 15
    stages_fg_tail(PX, PY, t2);    // bits 16..19

    scale_all(PX, PY, C1 * C2);

    const u32 a1 = base + ((u32)g5 << 10);
#pragma unroll
    for (int q = 0; q < 16; ++q) {
        float xl, xh, yl, yh;
        upk(PX[q], xl, xh); upk(PY[q], yl, yh);
        __stcs(&out[a1 + ((u32)(2 * q) << 15)],     make_float2(xl, yl));
        __stcs(&out[a1 + ((u32)(2 * q + 1) << 15)], make_float2(xh, yh));
    }
}

// ---------------------------------------------------------------------------
extern "C" void kernel_launch(void* const* d_in, const int* in_sizes, int n_in,
                              void* d_out, int out_size)
{
    const float* phi    = (const float*)d_in[0];   // [16, 2^20] float32
    const float* thetas = (const float*)d_in[1];   // [16, 20]   float32
    float2* out = (float2*)d_out;                  // [16, 2^20] (re, im)

    rx_a<<<2048, 256>>>(phi, thetas);
    rx_b<<<2048, 256>>>(thetas, out);
}